// round 11
// baseline (speedup 1.0000x reference)
#include <cuda_runtime.h>

#define Bsz 4
#define Nn  65536
#define Kk  16
#define Dd  16
#define NK  (Nn * Kk)            // 1048576 = 2^20
#define Ptot (Bsz * NK)          // 4194304
#define Tq   (Ptot / 4)          // quad-threads

// Scratch (allocation-free rule: __device__ globals)
// g_T: one 128B row per point: [f0..f15 | cx,cy,cz,pad | 3 x float4 pad] (32MB)
__device__ float4 g_T[(size_t)Bsz * Nn * 8];
__device__ float4 g_coordsPad[(size_t)Bsz * Nn];    // (B, N, 4) padded coords, 4MB
__device__ double g_M[35 * 32];                     // moments, 256B apart
__device__ float4 g_c1[16];                         // per-channel (W0, A.x, A.y, A.z) * scale
__device__ float4 g_c2[16];                         // per-channel (B.x, B.y, B.z, shift)

// ---------------------------------------------------------------------------
// Kernel 0: pad coords to float4 (into coordsPad AND g_T chunk 4), zero g_M
// ---------------------------------------------------------------------------
__global__ void __launch_bounds__(256)
k_pad(const float* __restrict__ coords) {
    int t = blockIdx.x * blockDim.x + threadIdx.x;   // 0 .. Bsz*Nn/4 - 1
    if (blockIdx.x == 0 && threadIdx.x < 35) g_M[threadIdx.x * 32] = 0.0;
    const float4* in = (const float4*)coords + (size_t)t * 3;
    float4 a = __ldg(in), bq = __ldg(in + 1), c = __ldg(in + 2);
    float4 p0 = make_float4(a.x, a.y, a.z, 0.f);
    float4 p1 = make_float4(a.w, bq.x, bq.y, 0.f);
    float4 p2 = make_float4(bq.z, bq.w, c.x, 0.f);
    float4 p3 = make_float4(c.y, c.z, c.w, 0.f);
    float4* o = g_coordsPad + (size_t)t * 4;
    o[0] = p0; o[1] = p1; o[2] = p2; o[3] = p3;
    size_t r = (size_t)t * 4 * 8;
    g_T[r + 4]      = p0;
    g_T[r + 8 + 4]  = p1;
    g_T[r + 16 + 4] = p2;
    g_T[r + 24 + 4] = p3;
}

// ---------------------------------------------------------------------------
// Kernel 1: moments of r7; blocks < 2048 also transpose one 128-point feature
// tile (B,D,N) -> g_T chunks 0-3 (stride 32 floats per point).
// ---------------------------------------------------------------------------
__global__ void __launch_bounds__(256)
k_stats(const int* __restrict__ idx, const float* __restrict__ feats) {
    __shared__ float tile[16][129];

    if (blockIdx.x < 2048) {
        int b   = blockIdx.x >> 9;
        int n0  = (blockIdx.x & 511) * 128;
        int tid = threadIdx.x;
        int nn = tid & 127;
        int dd = tid >> 7;                // 0..1
#pragma unroll
        for (int it = 0; it < 8; it++) {
            int d = dd + it * 2;
            tile[d][nn] = feats[((size_t)(b * 16 + d)) * Nn + n0 + nn];
        }
        __syncthreads();
        float* gTf = (float*)g_T;
        int d2 = tid & 15;
        int nb = tid >> 4;                // 0..15
#pragma unroll
        for (int it = 0; it < 8; it++) {
            int nn2 = nb + it * 16;
            gTf[((size_t)b * Nn + n0 + nn2) * 32 + d2] = tile[d2][nn2];
        }
    }

    float acc[35];
#pragma unroll
    for (int i = 0; i < 35; i++) acc[i] = 0.f;

    int t  = blockIdx.x * blockDim.x + threadIdx.x;   // 0 .. Tq-1
    int p0 = t << 2;
    int b  = p0 >> 20;
    int n  = (p0 >> 4) & (Nn - 1);

    int4 jj = ((const int4*)idx)[t];
    const float4* cb = g_coordsPad + (size_t)b * Nn;
    float4 ce = __ldg(cb + n);
    int js[4] = {jj.x, jj.y, jj.z, jj.w};

#pragma unroll
    for (int q = 0; q < 4; q++) {
        float4 cn = __ldg(cb + js[q]);
        float rx = ce.x - cn.x, ry = ce.y - cn.y, rz = ce.z - cn.z;
        float r[7];
        r[0] = sqrtf(rx * rx + ry * ry + rz * rz);
        r[1] = ce.x; r[2] = ce.y; r[3] = ce.z;
        r[4] = cn.x; r[5] = cn.y; r[6] = cn.z;
#pragma unroll
        for (int i = 0; i < 7; i++) acc[i] += r[i];
        int c = 7;
#pragma unroll
        for (int i = 0; i < 7; i++)
#pragma unroll
            for (int qq = i; qq < 7; qq++) acc[c++] += r[i] * r[qq];
    }

#pragma unroll
    for (int i = 0; i < 35; i++)
        for (int off = 16; off; off >>= 1)
            acc[i] += __shfl_down_sync(0xffffffffu, acc[i], off);

    __shared__ float s[8][35];
    int lane = threadIdx.x & 31, w = threadIdx.x >> 5;
    if (lane == 0) {
#pragma unroll
        for (int i = 0; i < 35; i++) s[w][i] = acc[i];
    }
    __syncthreads();
    if (threadIdx.x < 35) {
        float tt = 0.f;
#pragma unroll
        for (int w2 = 0; w2 < 8; w2++) tt += s[w2][threadIdx.x];
        atomicAdd(&g_M[threadIdx.x * 32], (double)tt);
    }
}

// ---------------------------------------------------------------------------
// Kernel 2: analytic BN stats per channel, fold into conv coefficients
// ---------------------------------------------------------------------------
__device__ __forceinline__ int tri_idx(int i, int j) {  // i <= j
    return i * 7 - i * (i - 1) / 2 + (j - i);
}

__global__ void k_finalize(const float* __restrict__ W, const float* __restrict__ bias,
                           const float* __restrict__ gamma, const float* __restrict__ beta) {
    int o = threadIdx.x;
    if (o >= 16) return;
    const double invP = 1.0 / (double)Ptot;
    double m[7];
#pragma unroll
    for (int i = 0; i < 7; i++) m[i] = g_M[i * 32] * invP;

    double a[7];
    a[0] = (double)W[o * 10 + 0];
#pragma unroll
    for (int i = 0; i < 3; i++) a[1 + i] = (double)W[o * 10 + 1 + i] + (double)W[o * 10 + 4 + i];
#pragma unroll
    for (int i = 0; i < 3; i++) a[4 + i] = (double)W[o * 10 + 7 + i] - (double)W[o * 10 + 1 + i];

    double mean = (double)bias[o];
#pragma unroll
    for (int i = 0; i < 7; i++) mean += a[i] * m[i];

    double var = 0.0;
    for (int i = 0; i < 7; i++)
        for (int j = 0; j < 7; j++) {
            int ii = i < j ? i : j, jj = i < j ? j : i;
            double C = g_M[(7 + tri_idx(ii, jj)) * 32] * invP - m[i] * m[j];
            var += a[i] * a[j] * C;
        }

    double scale = (double)gamma[o] * rsqrt(var + 1e-6);
    double shift = (double)beta[o] + ((double)bias[o] - mean) * scale;
    g_c1[o] = make_float4((float)(a[0] * scale), (float)(a[1] * scale),
                          (float)(a[2] * scale), (float)(a[3] * scale));
    g_c2[o] = make_float4((float)(a[4] * scale), (float)(a[5] * scale),
                          (float)(a[6] * scale), (float)shift);
}

// ---------------------------------------------------------------------------
// Kernel 3: main. 8-lane segments gather full 128B point-rows (feat + coords
// in one line -> 4 wavefronts per instruction). XOR-swizzled smem staging,
// then fully-coalesced channel-plane stores. dist recomputed in registers.
// ---------------------------------------------------------------------------
__global__ void __launch_bounds__(64)
k_main(const int* __restrict__ idx, float* __restrict__ out) {
    __shared__ float4 sm[2048];           // 8 segments x 32 rows x 8 slots (32KB)
    __shared__ float4 sc1[16], sc2[16];
    if (threadIdx.x < 16) { sc1[threadIdx.x] = g_c1[threadIdx.x]; sc2[threadIdx.x] = g_c2[threadIdx.x]; }
    __syncthreads();

    int t  = blockIdx.x * 64 + threadIdx.x;           // 0 .. Tq-1
    int p0 = t << 2;
    int b  = p0 >> 20;
    int n  = (p0 >> 4) & (Nn - 1);
    int o  = t & 3;                                    // own k-quad
    int lane = threadIdx.x & 31;
    int u8 = lane & 7;                                 // id within 8-lane segment; also chunk role
    float4* smseg = sm + (threadIdx.x >> 3) * 256;     // 8 segments per block

    int4 jj = ((const int4*)idx)[t];                   // own quad's neighbor indices
    float4 ce = __ldg(g_coordsPad + (size_t)b * Nn + n);

    const float4* fT = g_T + (size_t)b * Nn * 8;

    // ---- cooperative 128B-row gather: iteration v stages one row/segment ----
#pragma unroll
    for (int v = 0; v < 32; v++) {
        const int m = v & 3, u = v >> 2;
        int comp = (m == 0) ? jj.x : (m == 1) ? jj.y : (m == 2) ? jj.z : jj.w;
        int j = __shfl_sync(0xffffffffu, comp, u, 8);  // neighbor m of segment-thread u
        if (u8 < 5) {                                  // chunks 0-3 feat, 4 coords
            float4 val = __ldg(fT + (size_t)j * 8 + u8);
            smseg[v * 8 + (u8 ^ u)] = val;             // XOR slot swizzle (key = u)
        }
    }
    __syncwarp();

    // ---- feature half: read own rows (v = u8*4+m), coalesced plane stores ----
    float* ob = out + (size_t)b * 32 * NK + (size_t)n * 16 + 4 * o;
#pragma unroll
    for (int cc = 0; cc < 4; cc++) {
        int sl = cc ^ u8;
        float4 A = smseg[(u8 * 4 + 0) * 8 + sl];
        float4 B = smseg[(u8 * 4 + 1) * 8 + sl];
        float4 C = smseg[(u8 * 4 + 2) * 8 + sl];
        float4 E = smseg[(u8 * 4 + 3) * 8 + sl];
        __stcs((float4*)(ob + (size_t)(4 * cc + 0) * NK), make_float4(A.x, B.x, C.x, E.x));
        __stcs((float4*)(ob + (size_t)(4 * cc + 1) * NK), make_float4(A.y, B.y, C.y, E.y));
        __stcs((float4*)(ob + (size_t)(4 * cc + 2) * NK), make_float4(A.z, B.z, C.z, E.z));
        __stcs((float4*)(ob + (size_t)(4 * cc + 3) * NK), make_float4(A.w, B.w, C.w, E.w));
    }

    // ---- conv half: neighbor coords from chunk 4 of staged rows ------------
    int sl4 = 4 ^ u8;
    float4 c0 = smseg[(u8 * 4 + 0) * 8 + sl4];
    float4 c1 = smseg[(u8 * 4 + 1) * 8 + sl4];
    float4 c2 = smseg[(u8 * 4 + 2) * 8 + sl4];
    float4 c3 = smseg[(u8 * 4 + 3) * 8 + sl4];

    float rx, ry, rz;
    rx = ce.x - c0.x; ry = ce.y - c0.y; rz = ce.z - c0.z;
    float d0 = sqrtf(rx * rx + ry * ry + rz * rz);
    rx = ce.x - c1.x; ry = ce.y - c1.y; rz = ce.z - c1.z;
    float d1 = sqrtf(rx * rx + ry * ry + rz * rz);
    rx = ce.x - c2.x; ry = ce.y - c2.y; rz = ce.z - c2.z;
    float d2 = sqrtf(rx * rx + ry * ry + rz * rz);
    rx = ce.x - c3.x; ry = ce.y - c3.y; rz = ce.z - c3.z;
    float d3 = sqrtf(rx * rx + ry * ry + rz * rz);

    float* o2 = ob + (size_t)16 * NK;
#pragma unroll
    for (int d = 0; d < 16; d++) {
        float4 w1 = sc1[d], w2 = sc2[d];
        float ecom = fmaf(w1.y, ce.x, fmaf(w1.z, ce.y, fmaf(w1.w, ce.z, w2.w)));
        float v0 = fmaf(w1.x, d0, fmaf(w2.x, c0.x, fmaf(w2.y, c0.y, fmaf(w2.z, c0.z, ecom))));
        float v1 = fmaf(w1.x, d1, fmaf(w2.x, c1.x, fmaf(w2.y, c1.y, fmaf(w2.z, c1.z, ecom))));
        float v2 = fmaf(w1.x, d2, fmaf(w2.x, c2.x, fmaf(w2.y, c2.y, fmaf(w2.z, c2.z, ecom))));
        float v3 = fmaf(w1.x, d3, fmaf(w2.x, c3.x, fmaf(w2.y, c3.y, fmaf(w2.z, c3.z, ecom))));
        __stcs((float4*)(o2 + (size_t)d * NK),
               make_float4(fmaxf(v0, 0.f), fmaxf(v1, 0.f), fmaxf(v2, 0.f), fmaxf(v3, 0.f)));
    }
}

// ---------------------------------------------------------------------------
extern "C" void kernel_launch(void* const* d_in, const int* in_sizes, int n_in,
                              void* d_out, int out_size) {
    const float* coords = (const float*)d_in[0];
    const float* feats  = (const float*)d_in[1];
    const int*   idx    = (const int*)d_in[2];
    const float* W      = (const float*)d_in[3];
    const float* bias   = (const float*)d_in[4];
    const float* gamma  = (const float*)d_in[5];
    const float* beta   = (const float*)d_in[6];
    float*       out    = (float*)d_out;

    k_pad<<<(Bsz * Nn / 4) / 256, 256>>>(coords);
    k_stats<<<Tq / 256, 256>>>(idx, feats);
    k_finalize<<<1, 32>>>(W, bias, gamma, beta);
    k_main<<<Tq / 64, 64>>>(idx, out);
}

// round 12
// speedup vs baseline: 1.0362x; 1.0362x over previous
#include <cuda_runtime.h>

#define Bsz 4
#define Nn  65536
#define Kk  16
#define Dd  16
#define NK  (Nn * Kk)            // 1048576 = 2^20
#define Ptot (Bsz * NK)          // 4194304
#define Tq   (Ptot / 4)          // quad-threads (stats)
#define Tp   (Ptot / 2)          // pair-threads (main)

// Scratch (allocation-free rule: __device__ globals)
// g_T: one 128B row per point: [f0..f15 | cx,cy,cz,pad | 3 x float4 pad] (32MB)
__device__ float4 g_T[(size_t)Bsz * Nn * 8];
__device__ float4 g_coordsPad[(size_t)Bsz * Nn];    // (B, N, 4) padded coords, 4MB
__device__ double g_M[35 * 32];                     // moments, 256B apart
__device__ float4 g_c1[16];                         // per-channel (W0, A.x, A.y, A.z) * scale
__device__ float4 g_c2[16];                         // per-channel (B.x, B.y, B.z, shift)

// ---------------------------------------------------------------------------
// Kernel 0: pad coords to float4 (into coordsPad AND g_T chunk 4), zero g_M
// ---------------------------------------------------------------------------
__global__ void __launch_bounds__(256)
k_pad(const float* __restrict__ coords) {
    int t = blockIdx.x * blockDim.x + threadIdx.x;   // 0 .. Bsz*Nn/4 - 1
    if (blockIdx.x == 0 && threadIdx.x < 35) g_M[threadIdx.x * 32] = 0.0;
    const float4* in = (const float4*)coords + (size_t)t * 3;
    float4 a = __ldg(in), bq = __ldg(in + 1), c = __ldg(in + 2);
    float4 p0 = make_float4(a.x, a.y, a.z, 0.f);
    float4 p1 = make_float4(a.w, bq.x, bq.y, 0.f);
    float4 p2 = make_float4(bq.z, bq.w, c.x, 0.f);
    float4 p3 = make_float4(c.y, c.z, c.w, 0.f);
    float4* o = g_coordsPad + (size_t)t * 4;
    o[0] = p0; o[1] = p1; o[2] = p2; o[3] = p3;
    size_t r = (size_t)t * 4 * 8;
    g_T[r + 4]      = p0;
    g_T[r + 8 + 4]  = p1;
    g_T[r + 16 + 4] = p2;
    g_T[r + 24 + 4] = p3;
}

// ---------------------------------------------------------------------------
// Kernel 1: moments of r7; blocks < 2048 also transpose one 128-point feature
// tile (B,D,N) -> g_T chunks 0-3 (stride 32 floats per point).
// ---------------------------------------------------------------------------
__global__ void __launch_bounds__(256)
k_stats(const int* __restrict__ idx, const float* __restrict__ feats) {
    __shared__ float tile[16][129];

    if (blockIdx.x < 2048) {
        int b   = blockIdx.x >> 9;
        int n0  = (blockIdx.x & 511) * 128;
        int tid = threadIdx.x;
        int nn = tid & 127;
        int dd = tid >> 7;                // 0..1
#pragma unroll
        for (int it = 0; it < 8; it++) {
            int d = dd + it * 2;
            tile[d][nn] = feats[((size_t)(b * 16 + d)) * Nn + n0 + nn];
        }
        __syncthreads();
        float* gTf = (float*)g_T;
        int d2 = tid & 15;
        int nb = tid >> 4;                // 0..15
#pragma unroll
        for (int it = 0; it < 8; it++) {
            int nn2 = nb + it * 16;
            gTf[((size_t)b * Nn + n0 + nn2) * 32 + d2] = tile[d2][nn2];
        }
    }

    float acc[35];
#pragma unroll
    for (int i = 0; i < 35; i++) acc[i] = 0.f;

    int t  = blockIdx.x * blockDim.x + threadIdx.x;   // 0 .. Tq-1
    int p0 = t << 2;
    int b  = p0 >> 20;
    int n  = (p0 >> 4) & (Nn - 1);

    int4 jj = ((const int4*)idx)[t];
    const float4* cb = g_coordsPad + (size_t)b * Nn;
    float4 ce = __ldg(cb + n);
    int js[4] = {jj.x, jj.y, jj.z, jj.w};

#pragma unroll
    for (int q = 0; q < 4; q++) {
        float4 cn = __ldg(cb + js[q]);
        float rx = ce.x - cn.x, ry = ce.y - cn.y, rz = ce.z - cn.z;
        float r[7];
        r[0] = sqrtf(rx * rx + ry * ry + rz * rz);
        r[1] = ce.x; r[2] = ce.y; r[3] = ce.z;
        r[4] = cn.x; r[5] = cn.y; r[6] = cn.z;
#pragma unroll
        for (int i = 0; i < 7; i++) acc[i] += r[i];
        int c = 7;
#pragma unroll
        for (int i = 0; i < 7; i++)
#pragma unroll
            for (int qq = i; qq < 7; qq++) acc[c++] += r[i] * r[qq];
    }

#pragma unroll
    for (int i = 0; i < 35; i++)
        for (int off = 16; off; off >>= 1)
            acc[i] += __shfl_down_sync(0xffffffffu, acc[i], off);

    __shared__ float s[8][35];
    int lane = threadIdx.x & 31, w = threadIdx.x >> 5;
    if (lane == 0) {
#pragma unroll
        for (int i = 0; i < 35; i++) s[w][i] = acc[i];
    }
    __syncthreads();
    if (threadIdx.x < 35) {
        float tt = 0.f;
#pragma unroll
        for (int w2 = 0; w2 < 8; w2++) tt += s[w2][threadIdx.x];
        atomicAdd(&g_M[threadIdx.x * 32], (double)tt);
    }
}

// ---------------------------------------------------------------------------
// Kernel 2: analytic BN stats per channel, fold into conv coefficients
// ---------------------------------------------------------------------------
__device__ __forceinline__ int tri_idx(int i, int j) {  // i <= j
    return i * 7 - i * (i - 1) / 2 + (j - i);
}

__global__ void k_finalize(const float* __restrict__ W, const float* __restrict__ bias,
                           const float* __restrict__ gamma, const float* __restrict__ beta) {
    int o = threadIdx.x;
    if (o >= 16) return;
    const double invP = 1.0 / (double)Ptot;
    double m[7];
#pragma unroll
    for (int i = 0; i < 7; i++) m[i] = g_M[i * 32] * invP;

    double a[7];
    a[0] = (double)W[o * 10 + 0];
#pragma unroll
    for (int i = 0; i < 3; i++) a[1 + i] = (double)W[o * 10 + 1 + i] + (double)W[o * 10 + 4 + i];
#pragma unroll
    for (int i = 0; i < 3; i++) a[4 + i] = (double)W[o * 10 + 7 + i] - (double)W[o * 10 + 1 + i];

    double mean = (double)bias[o];
#pragma unroll
    for (int i = 0; i < 7; i++) mean += a[i] * m[i];

    double var = 0.0;
    for (int i = 0; i < 7; i++)
        for (int j = 0; j < 7; j++) {
            int ii = i < j ? i : j, jj = i < j ? j : i;
            double C = g_M[(7 + tri_idx(ii, jj)) * 32] * invP - m[i] * m[j];
            var += a[i] * a[j] * C;
        }

    double scale = (double)gamma[o] * rsqrt(var + 1e-6);
    double shift = (double)beta[o] + ((double)bias[o] - mean) * scale;
    g_c1[o] = make_float4((float)(a[0] * scale), (float)(a[1] * scale),
                          (float)(a[2] * scale), (float)(a[3] * scale));
    g_c2[o] = make_float4((float)(a[4] * scale), (float)(a[5] * scale),
                          (float)(a[6] * scale), (float)shift);
}

// ---------------------------------------------------------------------------
// Kernel 3: main. Thread = one k-PAIR. 8-lane segment = one n (16 rows).
// Each gather instruction reads one full 128B point-row (feat+coords) ->
// wavefront-optimal. 16KB smem staging, slot = chunk ^ (row>>1) swizzle
// (read phase hits all 8 float4-banks). float2 plane stores, coalesced.
// ---------------------------------------------------------------------------
__global__ void __launch_bounds__(64)
k_main(const int* __restrict__ idx, float* __restrict__ out) {
    __shared__ float4 sm[8 * 128];        // 8 segments x 16 rows x 8 slots = 16KB
    __shared__ float4 sc1[16], sc2[16];
    if (threadIdx.x < 16) { sc1[threadIdx.x] = g_c1[threadIdx.x]; sc2[threadIdx.x] = g_c2[threadIdx.x]; }
    __syncthreads();

    int t  = blockIdx.x * 64 + threadIdx.x;           // 0 .. Tp-1
    int p0 = t << 1;
    int b  = p0 >> 20;
    int n  = (p0 >> 4) & (Nn - 1);
    int u8 = t & 7;                                    // own k-pair id (k = 2*u8, 2*u8+1)
    float4* smseg = sm + (threadIdx.x >> 3) * 128;     // 8 segments per block

    int2 jj = ((const int2*)idx)[t];                   // own pair's neighbor indices
    float4 ce = __ldg(g_coordsPad + (size_t)b * Nn + n);

    const float4* fT = g_T + (size_t)b * Nn * 8;

    // ---- cooperative 128B-row gather: v = row (owner u = v>>1, comp m = v&1)
#pragma unroll 8
    for (int v = 0; v < 16; v++) {
        int m = v & 1, u = v >> 1;
        int j = __shfl_sync(0xffffffffu, m ? jj.y : jj.x, u, 8);
        if (u8 < 5) {                                  // chunks 0-3 feat, 4 coords
            float4 val = __ldg(fT + (size_t)j * 8 + u8);
            smseg[v * 8 + (u8 ^ u)] = val;             // slot = chunk ^ owner
        }
    }
    __syncwarp();

    // ---- feature half: own rows are v = 2*u8 + m; coalesced float2 planes ----
    float* ob = out + (size_t)b * 32 * NK + (size_t)n * 16 + 2 * u8;
    int r0 = 2 * u8, r1 = 2 * u8 + 1;
#pragma unroll
    for (int c = 0; c < 4; c++) {
        int sl = c ^ u8;
        float4 A = smseg[r0 * 8 + sl];                 // chunk c of neighbor 0
        float4 B = smseg[r1 * 8 + sl];                 // chunk c of neighbor 1
        *(float2*)(ob + (size_t)(4 * c + 0) * NK) = make_float2(A.x, B.x);
        *(float2*)(ob + (size_t)(4 * c + 1) * NK) = make_float2(A.y, B.y);
        *(float2*)(ob + (size_t)(4 * c + 2) * NK) = make_float2(A.z, B.z);
        *(float2*)(ob + (size_t)(4 * c + 3) * NK) = make_float2(A.w, B.w);
    }

    // ---- conv half: neighbor coords from chunk 4 ---------------------------
    int sl4 = 4 ^ u8;
    float4 c0 = smseg[r0 * 8 + sl4];
    float4 c1 = smseg[r1 * 8 + sl4];

    float rx, ry, rz;
    rx = ce.x - c0.x; ry = ce.y - c0.y; rz = ce.z - c0.z;
    float d0 = sqrtf(rx * rx + ry * ry + rz * rz);
    rx = ce.x - c1.x; ry = ce.y - c1.y; rz = ce.z - c1.z;
    float d1 = sqrtf(rx * rx + ry * ry + rz * rz);

    float* o2 = ob + (size_t)16 * NK;
#pragma unroll
    for (int d = 0; d < 16; d++) {
        float4 w1 = sc1[d], w2 = sc2[d];
        float ecom = fmaf(w1.y, ce.x, fmaf(w1.z, ce.y, fmaf(w1.w, ce.z, w2.w)));
        float v0 = fmaf(w1.x, d0, fmaf(w2.x, c0.x, fmaf(w2.y, c0.y, fmaf(w2.z, c0.z, ecom))));
        float v1 = fmaf(w1.x, d1, fmaf(w2.x, c1.x, fmaf(w2.y, c1.y, fmaf(w2.z, c1.z, ecom))));
        *(float2*)(o2 + (size_t)d * NK) = make_float2(fmaxf(v0, 0.f), fmaxf(v1, 0.f));
    }
}

// ---------------------------------------------------------------------------
extern "C" void kernel_launch(void* const* d_in, const int* in_sizes, int n_in,
                              void* d_out, int out_size) {
    const float* coords = (const float*)d_in[0];
    const float* feats  = (const float*)d_in[1];
    const int*   idx    = (const int*)d_in[2];
    const float* W      = (const float*)d_in[3];
    const float* bias   = (const float*)d_in[4];
    const float* gamma  = (const float*)d_in[5];
    const float* beta   = (const float*)d_in[6];
    float*       out    = (float*)d_out;

    k_pad<<<(Bsz * Nn / 4) / 256, 256>>>(coords);
    k_stats<<<Tq / 256, 256>>>(idx, feats);
    k_finalize<<<1, 32>>>(W, bias, gamma, beta);
    k_main<<<Tp / 64, 64>>>(idx, out);
}

// round 13
// speedup vs baseline: 1.2535x; 1.2097x over previous
#include <cuda_runtime.h>

#define Bsz 4
#define Nn  65536
#define Kk  16
#define Dd  16
#define NK  (Nn * Kk)            // 1048576 = 2^20
#define Ptot (Bsz * NK)          // 4194304
#define Tq   (Ptot / 4)          // quad-threads

// Scratch (allocation-free rule: __device__ globals)
__device__ float  g_featT[(size_t)Bsz * Nn * Dd];   // (B, N, D) transposed features, 16MB
__device__ float4 g_coordsPad[(size_t)Bsz * Nn];    // (B, N, 4) padded coords, 4MB
__device__ double g_M[35 * 32];                     // moments, 256B apart (zero-init; re-zeroed by finalize)
__device__ float4 g_c1[16];                         // per-channel (W0, A.x, A.y, A.z) * scale
__device__ float4 g_c2[16];                         // per-channel (B.x, B.y, B.z, shift)

// logical slot layout (matches original 35-moment scheme):
// [0..6]=first moments (dist, ext3, nbr3); [7..34]=upper-tri second moments
__constant__ int c_padSlot[9]   = {1, 2, 3, 14, 15, 16, 20, 21, 25};   // ext, ext*ext
__constant__ int c_statSlot[26] = {0, 4, 5, 6, 7, 8, 9, 10, 11, 12, 13,
                                   17, 18, 19, 22, 23, 24, 26, 27, 28,
                                   29, 30, 31, 32, 33, 34};

// ---------------------------------------------------------------------------
// Kernel 0: pad coords to float4 AND accumulate pure-ext moments (x16 weight).
// ---------------------------------------------------------------------------
__global__ void __launch_bounds__(256)
k_pad(const float* __restrict__ coords) {
    int t = blockIdx.x * blockDim.x + threadIdx.x;   // 0 .. Bsz*Nn/4 - 1
    const float4* in = (const float4*)coords + (size_t)t * 3;
    float4 a = __ldg(in), bq = __ldg(in + 1), c = __ldg(in + 2);
    float4 p0 = make_float4(a.x, a.y, a.z, 0.f);
    float4 p1 = make_float4(a.w, bq.x, bq.y, 0.f);
    float4 p2 = make_float4(bq.z, bq.w, c.x, 0.f);
    float4 p3 = make_float4(c.y, c.z, c.w, 0.f);
    float4* o = g_coordsPad + (size_t)t * 4;
    o[0] = p0; o[1] = p1; o[2] = p2; o[3] = p3;

    // per-point ext moments over this thread's 4 points
    float v[9];
    v[0] = p0.x + p1.x + p2.x + p3.x;
    v[1] = p0.y + p1.y + p2.y + p3.y;
    v[2] = p0.z + p1.z + p2.z + p3.z;
    v[3] = p0.x * p0.x + p1.x * p1.x + p2.x * p2.x + p3.x * p3.x;
    v[4] = p0.x * p0.y + p1.x * p1.y + p2.x * p2.y + p3.x * p3.y;
    v[5] = p0.x * p0.z + p1.x * p1.z + p2.x * p2.z + p3.x * p3.z;
    v[6] = p0.y * p0.y + p1.y * p1.y + p2.y * p2.y + p3.y * p3.y;
    v[7] = p0.y * p0.z + p1.y * p1.z + p2.y * p2.z + p3.y * p3.z;
    v[8] = p0.z * p0.z + p1.z * p1.z + p2.z * p2.z + p3.z * p3.z;

#pragma unroll
    for (int i = 0; i < 9; i++)
        for (int off = 16; off; off >>= 1)
            v[i] += __shfl_down_sync(0xffffffffu, v[i], off);

    __shared__ float s[8][9];
    int lane = threadIdx.x & 31, w = threadIdx.x >> 5;
    if (lane == 0) {
#pragma unroll
        for (int i = 0; i < 9; i++) s[w][i] = v[i];
    }
    __syncthreads();
    if (threadIdx.x < 9) {
        float tt = 0.f;
#pragma unroll
        for (int w2 = 0; w2 < 8; w2++) tt += s[w2][threadIdx.x];
        atomicAdd(&g_M[c_padSlot[threadIdx.x] * 32], 16.0 * (double)tt);
    }
}

// ---------------------------------------------------------------------------
// Kernel 1: gather-dependent moments (26 of 35), cross-terms factored per
// thread; blocks < 2048 also transpose one feature tile (B,D,N)->(B,N,D).
// ---------------------------------------------------------------------------
__global__ void __launch_bounds__(256)
k_stats(const int* __restrict__ idx, const float* __restrict__ feats) {
    __shared__ float tile[16][129];

    if (blockIdx.x < 2048) {
        int b   = blockIdx.x >> 9;
        int n0  = (blockIdx.x & 511) * 128;
        int tid = threadIdx.x;
        int nn = tid & 127;
        int dd = tid >> 7;                // 0..1
#pragma unroll
        for (int it = 0; it < 8; it++) {
            int d = dd + it * 2;
            tile[d][nn] = feats[((size_t)(b * 16 + d)) * Nn + n0 + nn];
        }
        __syncthreads();
        int d2 = tid & 15;
        int nb = tid >> 4;                // 0..15
#pragma unroll
        for (int it = 0; it < 8; it++) {
            int nn2 = nb + it * 16;
            g_featT[((size_t)b * Nn + n0 + nn2) * 16 + d2] = tile[d2][nn2];
        }
    }

    int t  = blockIdx.x * blockDim.x + threadIdx.x;   // 0 .. Tq-1
    int p0 = t << 2;
    int b  = p0 >> 20;
    int n  = (p0 >> 4) & (Nn - 1);

    int4 jj = ((const int4*)idx)[t];
    const float4* cb = g_coordsPad + (size_t)b * Nn;
    float4 ce  = __ldg(cb + n);
    float4 cn0 = __ldg(cb + jj.x);
    float4 cn1 = __ldg(cb + jj.y);
    float4 cn2 = __ldg(cb + jj.z);
    float4 cn3 = __ldg(cb + jj.w);

    float rx, ry, rz;
    rx = ce.x - cn0.x; ry = ce.y - cn0.y; rz = ce.z - cn0.z;
    float d0 = sqrtf(rx * rx + ry * ry + rz * rz);
    rx = ce.x - cn1.x; ry = ce.y - cn1.y; rz = ce.z - cn1.z;
    float d1 = sqrtf(rx * rx + ry * ry + rz * rz);
    rx = ce.x - cn2.x; ry = ce.y - cn2.y; rz = ce.z - cn2.z;
    float d2 = sqrtf(rx * rx + ry * ry + rz * rz);
    rx = ce.x - cn3.x; ry = ce.y - cn3.y; rz = ce.z - cn3.z;
    float d3 = sqrtf(rx * rx + ry * ry + rz * rz);

    float sd  = d0 + d1 + d2 + d3;
    float sd2 = d0 * d0 + d1 * d1 + d2 * d2 + d3 * d3;
    float snx = cn0.x + cn1.x + cn2.x + cn3.x;
    float sny = cn0.y + cn1.y + cn2.y + cn3.y;
    float snz = cn0.z + cn1.z + cn2.z + cn3.z;
    float dnx = d0 * cn0.x + d1 * cn1.x + d2 * cn2.x + d3 * cn3.x;
    float dny = d0 * cn0.y + d1 * cn1.y + d2 * cn2.y + d3 * cn3.y;
    float dnz = d0 * cn0.z + d1 * cn1.z + d2 * cn2.z + d3 * cn3.z;
    float nxx = cn0.x * cn0.x + cn1.x * cn1.x + cn2.x * cn2.x + cn3.x * cn3.x;
    float nxy = cn0.x * cn0.y + cn1.x * cn1.y + cn2.x * cn2.y + cn3.x * cn3.y;
    float nxz = cn0.x * cn0.z + cn1.x * cn1.z + cn2.x * cn2.z + cn3.x * cn3.z;
    float nyy = cn0.y * cn0.y + cn1.y * cn1.y + cn2.y * cn2.y + cn3.y * cn3.y;
    float nyz = cn0.y * cn0.z + cn1.y * cn1.z + cn2.y * cn2.z + cn3.y * cn3.z;
    float nzz = cn0.z * cn0.z + cn1.z * cn1.z + cn2.z * cn2.z + cn3.z * cn3.z;

    float v[26] = {
        sd, snx, sny, snz, sd2,
        ce.x * sd, ce.y * sd, ce.z * sd,
        dnx, dny, dnz,
        ce.x * snx, ce.x * sny, ce.x * snz,
        ce.y * snx, ce.y * sny, ce.y * snz,
        ce.z * snx, ce.z * sny, ce.z * snz,
        nxx, nxy, nxz, nyy, nyz, nzz };

#pragma unroll
    for (int i = 0; i < 26; i++)
        for (int off = 16; off; off >>= 1)
            v[i] += __shfl_down_sync(0xffffffffu, v[i], off);

    __shared__ float s[8][26];
    int lane = threadIdx.x & 31, w = threadIdx.x >> 5;
    if (lane == 0) {
#pragma unroll
        for (int i = 0; i < 26; i++) s[w][i] = v[i];
    }
    __syncthreads();
    if (threadIdx.x < 26) {
        float tt = 0.f;
#pragma unroll
        for (int w2 = 0; w2 < 8; w2++) tt += s[w2][threadIdx.x];
        atomicAdd(&g_M[c_statSlot[threadIdx.x] * 32], (double)tt);
    }
}

// ---------------------------------------------------------------------------
// Kernel 2: analytic BN stats per channel -> conv coefficients; then re-zero
// g_M for the next graph replay (g_M is zero-init at module load).
// ---------------------------------------------------------------------------
__device__ __forceinline__ int tri_idx(int i, int j) {  // i <= j
    return i * 7 - i * (i - 1) / 2 + (j - i);
}

__global__ void k_finalize(const float* __restrict__ W, const float* __restrict__ bias,
                           const float* __restrict__ gamma, const float* __restrict__ beta) {
    int o = threadIdx.x;
    if (o < 16) {
        const double invP = 1.0 / (double)Ptot;
        double m[7];
#pragma unroll
        for (int i = 0; i < 7; i++) m[i] = g_M[i * 32] * invP;

        double a[7];
        a[0] = (double)W[o * 10 + 0];
#pragma unroll
        for (int i = 0; i < 3; i++) a[1 + i] = (double)W[o * 10 + 1 + i] + (double)W[o * 10 + 4 + i];
#pragma unroll
        for (int i = 0; i < 3; i++) a[4 + i] = (double)W[o * 10 + 7 + i] - (double)W[o * 10 + 1 + i];

        double mean = (double)bias[o];
#pragma unroll
        for (int i = 0; i < 7; i++) mean += a[i] * m[i];

        double var = 0.0;
        for (int i = 0; i < 7; i++)
            for (int j = 0; j < 7; j++) {
                int ii = i < j ? i : j, jj = i < j ? j : i;
                double C = g_M[(7 + tri_idx(ii, jj)) * 32] * invP - m[i] * m[j];
                var += a[i] * a[j] * C;
            }

        double scale = (double)gamma[o] * rsqrt(var + 1e-6);
        double shift = (double)beta[o] + ((double)bias[o] - mean) * scale;
        g_c1[o] = make_float4((float)(a[0] * scale), (float)(a[1] * scale),
                              (float)(a[2] * scale), (float)(a[3] * scale));
        g_c2[o] = make_float4((float)(a[4] * scale), (float)(a[5] * scale),
                              (float)(a[6] * scale), (float)shift);
    }
    __syncthreads();
    if (threadIdx.x < 35) g_M[threadIdx.x * 32] = 0.0;   // reset for next replay
}

// ---------------------------------------------------------------------------
// Kernel 3: main (R10 verbatim — proven best). Front-batched scattered loads,
// cooperative feature gather + XOR smem transpose + coalesced plane stores.
// ---------------------------------------------------------------------------
__global__ void __launch_bounds__(128)
k_main(const int* __restrict__ idx, float* __restrict__ out) {
    __shared__ float4 sm[32 * 68];        // 32 groups x (16 slots x 4 chunks + 4 pad)
    __shared__ float4 sc1[16], sc2[16];
    if (threadIdx.x < 16) { sc1[threadIdx.x] = g_c1[threadIdx.x]; sc2[threadIdx.x] = g_c2[threadIdx.x]; }
    __syncthreads();

    int t  = blockIdx.x * blockDim.x + threadIdx.x;   // 0 .. Tq-1
    int p0 = t << 2;
    int b  = p0 >> 20;
    int n  = (p0 >> 4) & (Nn - 1);
    int o  = t & 3;                                    // own k-quad (= lane&3)

    int4 jj = ((const int4*)idx)[t];                   // own quad's neighbor indices

    // issue coord gathers early; consumed after the feature phase
    const float4* cb = g_coordsPad + (size_t)b * Nn;
    float4 ce = __ldg(cb + n);
    float4 c0 = __ldg(cb + jj.x);
    float4 c1 = __ldg(cb + jj.y);
    float4 c2 = __ldg(cb + jj.z);
    float4 c3 = __ldg(cb + jj.w);

    const float4* fT = (const float4*)(g_featT + (size_t)b * Nn * 16);
    float4* smg = sm + (threadIdx.x >> 2) * 68;

    // ---- cooperative gather: iteration u stages quad u's 4 rows ----------
#pragma unroll
    for (int u = 0; u < 4; u++) {
        int j0 = __shfl_sync(0xffffffffu, jj.x, u, 4);
        int j1 = __shfl_sync(0xffffffffu, jj.y, u, 4);
        int j2 = __shfl_sync(0xffffffffu, jj.z, u, 4);
        int j3 = __shfl_sync(0xffffffffu, jj.w, u, 4);
        float4 v0 = __ldg(fT + (size_t)j0 * 4 + o);    // chunk o of row j0
        float4 v1 = __ldg(fT + (size_t)j1 * 4 + o);
        float4 v2 = __ldg(fT + (size_t)j2 * 4 + o);
        float4 v3 = __ldg(fT + (size_t)j3 * 4 + o);
        int sw = o ^ u;                                // XOR swizzle position
        smg[(4 * u + 0) * 4 + sw] = v0;
        smg[(4 * u + 1) * 4 + sw] = v1;
        smg[(4 * u + 2) * 4 + sw] = v2;
        smg[(4 * u + 3) * 4 + sw] = v3;
    }
    __syncwarp();

    // ---- read back own quad, store fully-coalesced channel planes --------
    float* ob = out + (size_t)b * 32 * NK + (size_t)n * 16 + 4 * o;
#pragma unroll
    for (int q = 0; q < 4; q++) {
        int sw = q ^ o;
        float4 A = smg[(4 * o + 0) * 4 + sw];          // chunk q of own neighbor 0..3
        float4 B = smg[(4 * o + 1) * 4 + sw];
        float4 C = smg[(4 * o + 2) * 4 + sw];
        float4 E = smg[(4 * o + 3) * 4 + sw];
        __stcs((float4*)(ob + (size_t)(4 * q + 0) * NK), make_float4(A.x, B.x, C.x, E.x));
        __stcs((float4*)(ob + (size_t)(4 * q + 1) * NK), make_float4(A.y, B.y, C.y, E.y));
        __stcs((float4*)(ob + (size_t)(4 * q + 2) * NK), make_float4(A.z, B.z, C.z, E.z));
        __stcs((float4*)(ob + (size_t)(4 * q + 3) * NK), make_float4(A.w, B.w, C.w, E.w));
    }

    // ---- conv half: recomputed geometry ------------------------------------
    float rx, ry, rz;
    rx = ce.x - c0.x; ry = ce.y - c0.y; rz = ce.z - c0.z;
    float d0 = sqrtf(rx * rx + ry * ry + rz * rz);
    rx = ce.x - c1.x; ry = ce.y - c1.y; rz = ce.z - c1.z;
    float d1 = sqrtf(rx * rx + ry * ry + rz * rz);
    rx = ce.x - c2.x; ry = ce.y - c2.y; rz = ce.z - c2.z;
    float d2 = sqrtf(rx * rx + ry * ry + rz * rz);
    rx = ce.x - c3.x; ry = ce.y - c3.y; rz = ce.z - c3.z;
    float d3 = sqrtf(rx * rx + ry * ry + rz * rz);

    float* o2 = ob + (size_t)16 * NK;
#pragma unroll
    for (int d = 0; d < 16; d++) {
        float4 w1 = sc1[d], w2 = sc2[d];
        float ecom = fmaf(w1.y, ce.x, fmaf(w1.z, ce.y, fmaf(w1.w, ce.z, w2.w)));
        float v0 = fmaf(w1.x, d0, fmaf(w2.x, c0.x, fmaf(w2.y, c0.y, fmaf(w2.z, c0.z, ecom))));
        float v1 = fmaf(w1.x, d1, fmaf(w2.x, c1.x, fmaf(w2.y, c1.y, fmaf(w2.z, c1.z, ecom))));
        float v2 = fmaf(w1.x, d2, fmaf(w2.x, c2.x, fmaf(w2.y, c2.y, fmaf(w2.z, c2.z, ecom))));
        float v3 = fmaf(w1.x, d3, fmaf(w2.x, c3.x, fmaf(w2.y, c3.y, fmaf(w2.z, c3.z, ecom))));
        __stcs((float4*)(o2 + (size_t)d * NK),
               make_float4(fmaxf(v0, 0.f), fmaxf(v1, 0.f), fmaxf(v2, 0.f), fmaxf(v3, 0.f)));
    }
}

// ---------------------------------------------------------------------------
extern "C" void kernel_launch(void* const* d_in, const int* in_sizes, int n_in,
                              void* d_out, int out_size) {
    const float* coords = (const float*)d_in[0];
    const float* feats  = (const float*)d_in[1];
    const int*   idx    = (const int*)d_in[2];
    const float* W      = (const float*)d_in[3];
    const float* bias   = (const float*)d_in[4];
    const float* gamma  = (const float*)d_in[5];
    const float* beta   = (const float*)d_in[6];
    float*       out    = (float*)d_out;

    k_pad<<<(Bsz * Nn / 4) / 256, 256>>>(coords);
    k_stats<<<Tq / 256, 256>>>(idx, feats);
    k_finalize<<<1, 64>>>(W, bias, gamma, beta);
    k_main<<<Tq / 128, 128>>>(idx, out);
}

// round 14
// speedup vs baseline: 1.3293x; 1.0605x over previous
#include <cuda_runtime.h>

#define Bsz 4
#define Nn  65536
#define Kk  16
#define Dd  16
#define NK  (Nn * Kk)            // 1048576 = 2^20
#define Ptot (Bsz * NK)          // 4194304
#define Tq   (Ptot / 4)          // quad-threads (main)
#define T8   (Ptot / 8)          // oct-threads (stats)

// Scratch (allocation-free rule: __device__ globals)
__device__ float  g_featT[(size_t)Bsz * Nn * Dd];   // (B, N, D) transposed features, 16MB
__device__ float4 g_coordsPad[(size_t)Bsz * Nn];    // (B, N, 4) padded coords, 4MB
__device__ double g_M[35 * 32];                     // moments, 256B apart (zero-init; re-zeroed by finalize)
__device__ float4 g_c1[16];                         // per-channel (W0, A.x, A.y, A.z) * scale
__device__ float4 g_c2[16];                         // per-channel (B.x, B.y, B.z, shift)

// logical slot layout: [0..6]=first moments (dist, ext3, nbr3); [7..34]=upper-tri second
__constant__ int c_padSlot[9]   = {1, 2, 3, 14, 15, 16, 20, 21, 25};   // ext, ext*ext
__constant__ int c_statSlot[26] = {0, 4, 5, 6, 7, 8, 9, 10, 11, 12, 13,
                                   17, 18, 19, 22, 23, 24, 26, 27, 28,
                                   29, 30, 31, 32, 33, 34};

// ---------------------------------------------------------------------------
// Kernel 0: pad coords to float4 AND accumulate pure-ext moments (x16 weight).
// ---------------------------------------------------------------------------
__global__ void __launch_bounds__(256)
k_pad(const float* __restrict__ coords) {
    int t = blockIdx.x * blockDim.x + threadIdx.x;   // 0 .. Bsz*Nn/4 - 1
    const float4* in = (const float4*)coords + (size_t)t * 3;
    float4 a = __ldg(in), bq = __ldg(in + 1), c = __ldg(in + 2);
    float4 p0 = make_float4(a.x, a.y, a.z, 0.f);
    float4 p1 = make_float4(a.w, bq.x, bq.y, 0.f);
    float4 p2 = make_float4(bq.z, bq.w, c.x, 0.f);
    float4 p3 = make_float4(c.y, c.z, c.w, 0.f);
    float4* o = g_coordsPad + (size_t)t * 4;
    o[0] = p0; o[1] = p1; o[2] = p2; o[3] = p3;

    float v[9];
    v[0] = p0.x + p1.x + p2.x + p3.x;
    v[1] = p0.y + p1.y + p2.y + p3.y;
    v[2] = p0.z + p1.z + p2.z + p3.z;
    v[3] = p0.x * p0.x + p1.x * p1.x + p2.x * p2.x + p3.x * p3.x;
    v[4] = p0.x * p0.y + p1.x * p1.y + p2.x * p2.y + p3.x * p3.y;
    v[5] = p0.x * p0.z + p1.x * p1.z + p2.x * p2.z + p3.x * p3.z;
    v[6] = p0.y * p0.y + p1.y * p1.y + p2.y * p2.y + p3.y * p3.y;
    v[7] = p0.y * p0.z + p1.y * p1.z + p2.y * p2.z + p3.y * p3.z;
    v[8] = p0.z * p0.z + p1.z * p1.z + p2.z * p2.z + p3.z * p3.z;

#pragma unroll
    for (int i = 0; i < 9; i++)
        for (int off = 16; off; off >>= 1)
            v[i] += __shfl_down_sync(0xffffffffu, v[i], off);

    __shared__ float s[8][9];
    int lane = threadIdx.x & 31, w = threadIdx.x >> 5;
    if (lane == 0) {
#pragma unroll
        for (int i = 0; i < 9; i++) s[w][i] = v[i];
    }
    __syncthreads();
    if (threadIdx.x < 9) {
        float tt = 0.f;
#pragma unroll
        for (int w2 = 0; w2 < 8; w2++) tt += s[w2][threadIdx.x];
        atomicAdd(&g_M[c_padSlot[threadIdx.x] * 32], 16.0 * (double)tt);
    }
}

// ---------------------------------------------------------------------------
// Kernel 1: gather-dependent moments, 8 pairs per thread (high MLP); every
// block (2048 total) also transposes one feature tile (B,D,N)->(B,N,D).
// ---------------------------------------------------------------------------
__global__ void __launch_bounds__(256)
k_stats(const int* __restrict__ idx, const float* __restrict__ feats) {
    __shared__ float tile[16][129];

    {   // transpose one 128-point tile (grid is exactly 2048 blocks)
        int b   = blockIdx.x >> 9;
        int n0  = (blockIdx.x & 511) * 128;
        int tid = threadIdx.x;
        int nn = tid & 127;
        int dd = tid >> 7;                // 0..1
#pragma unroll
        for (int it = 0; it < 8; it++) {
            int d = dd + it * 2;
            tile[d][nn] = feats[((size_t)(b * 16 + d)) * Nn + n0 + nn];
        }
        __syncthreads();
        int d2 = tid & 15;
        int nb = tid >> 4;                // 0..15
#pragma unroll
        for (int it = 0; it < 8; it++) {
            int nn2 = nb + it * 16;
            g_featT[((size_t)b * Nn + n0 + nn2) * 16 + d2] = tile[d2][nn2];
        }
    }

    int t  = blockIdx.x * blockDim.x + threadIdx.x;   // 0 .. T8-1
    int p0 = t << 3;                                   // 8 pairs, same center n
    int b  = p0 >> 20;
    int n  = (p0 >> 4) & (Nn - 1);

    int4 ja = ((const int4*)idx)[2 * t];
    int4 jb = ((const int4*)idx)[2 * t + 1];
    const float4* cb = g_coordsPad + (size_t)b * Nn;
    float4 ce = __ldg(cb + n);

    float4 cn[8];
    cn[0] = __ldg(cb + ja.x); cn[1] = __ldg(cb + ja.y);
    cn[2] = __ldg(cb + ja.z); cn[3] = __ldg(cb + ja.w);
    cn[4] = __ldg(cb + jb.x); cn[5] = __ldg(cb + jb.y);
    cn[6] = __ldg(cb + jb.z); cn[7] = __ldg(cb + jb.w);

    float dd[8];
#pragma unroll
    for (int i = 0; i < 8; i++) {
        float rx = ce.x - cn[i].x, ry = ce.y - cn[i].y, rz = ce.z - cn[i].z;
        dd[i] = sqrtf(rx * rx + ry * ry + rz * rz);
    }

    float sd = 0.f, sd2 = 0.f, snx = 0.f, sny = 0.f, snz = 0.f;
    float dnx = 0.f, dny = 0.f, dnz = 0.f;
    float nxx = 0.f, nxy = 0.f, nxz = 0.f, nyy = 0.f, nyz = 0.f, nzz = 0.f;
#pragma unroll
    for (int i = 0; i < 8; i++) {
        float x = cn[i].x, y = cn[i].y, z = cn[i].z, d = dd[i];
        sd += d;        sd2 = fmaf(d, d, sd2);
        snx += x;       sny += y;       snz += z;
        dnx = fmaf(d, x, dnx); dny = fmaf(d, y, dny); dnz = fmaf(d, z, dnz);
        nxx = fmaf(x, x, nxx); nxy = fmaf(x, y, nxy); nxz = fmaf(x, z, nxz);
        nyy = fmaf(y, y, nyy); nyz = fmaf(y, z, nyz); nzz = fmaf(z, z, nzz);
    }

    float v[26] = {
        sd, snx, sny, snz, sd2,
        ce.x * sd, ce.y * sd, ce.z * sd,
        dnx, dny, dnz,
        ce.x * snx, ce.x * sny, ce.x * snz,
        ce.y * snx, ce.y * sny, ce.y * snz,
        ce.z * snx, ce.z * sny, ce.z * snz,
        nxx, nxy, nxz, nyy, nyz, nzz };

#pragma unroll
    for (int i = 0; i < 26; i++)
        for (int off = 16; off; off >>= 1)
            v[i] += __shfl_down_sync(0xffffffffu, v[i], off);

    __shared__ float s[8][26];
    int lane = threadIdx.x & 31, w = threadIdx.x >> 5;
    if (lane == 0) {
#pragma unroll
        for (int i = 0; i < 26; i++) s[w][i] = v[i];
    }
    __syncthreads();
    if (threadIdx.x < 26) {
        float tt = 0.f;
#pragma unroll
        for (int w2 = 0; w2 < 8; w2++) tt += s[w2][threadIdx.x];
        atomicAdd(&g_M[c_statSlot[threadIdx.x] * 32], (double)tt);
    }
}

// ---------------------------------------------------------------------------
// Kernel 2: analytic BN stats per channel -> conv coefficients; then re-zero
// g_M for the next graph replay (g_M is zero-init at module load).
// ---------------------------------------------------------------------------
__device__ __forceinline__ int tri_idx(int i, int j) {  // i <= j
    return i * 7 - i * (i - 1) / 2 + (j - i);
}

__global__ void k_finalize(const float* __restrict__ W, const float* __restrict__ bias,
                           const float* __restrict__ gamma, const float* __restrict__ beta) {
    int o = threadIdx.x;
    if (o < 16) {
        const double invP = 1.0 / (double)Ptot;
        double m[7];
#pragma unroll
        for (int i = 0; i < 7; i++) m[i] = g_M[i * 32] * invP;

        double a[7];
        a[0] = (double)W[o * 10 + 0];
#pragma unroll
        for (int i = 0; i < 3; i++) a[1 + i] = (double)W[o * 10 + 1 + i] + (double)W[o * 10 + 4 + i];
#pragma unroll
        for (int i = 0; i < 3; i++) a[4 + i] = (double)W[o * 10 + 7 + i] - (double)W[o * 10 + 1 + i];

        double mean = (double)bias[o];
#pragma unroll
        for (int i = 0; i < 7; i++) mean += a[i] * m[i];

        double var = 0.0;
        for (int i = 0; i < 7; i++)
            for (int j = 0; j < 7; j++) {
                int ii = i < j ? i : j, jj = i < j ? j : i;
                double C = g_M[(7 + tri_idx(ii, jj)) * 32] * invP - m[i] * m[j];
                var += a[i] * a[j] * C;
            }

        double scale = (double)gamma[o] * rsqrt(var + 1e-6);
        double shift = (double)beta[o] + ((double)bias[o] - mean) * scale;
        g_c1[o] = make_float4((float)(a[0] * scale), (float)(a[1] * scale),
                              (float)(a[2] * scale), (float)(a[3] * scale));
        g_c2[o] = make_float4((float)(a[4] * scale), (float)(a[5] * scale),
                              (float)(a[6] * scale), (float)shift);
    }
    __syncthreads();
    if (threadIdx.x < 35) g_M[threadIdx.x * 32] = 0.0;   // reset for next replay
}

// ---------------------------------------------------------------------------
// Kernel 3: main (R10 verbatim — proven best). Front-batched scattered loads,
// cooperative feature gather + XOR smem transpose + coalesced plane stores.
// ---------------------------------------------------------------------------
__global__ void __launch_bounds__(128)
k_main(const int* __restrict__ idx, float* __restrict__ out) {
    __shared__ float4 sm[32 * 68];        // 32 groups x (16 slots x 4 chunks + 4 pad)
    __shared__ float4 sc1[16], sc2[16];
    if (threadIdx.x < 16) { sc1[threadIdx.x] = g_c1[threadIdx.x]; sc2[threadIdx.x] = g_c2[threadIdx.x]; }
    __syncthreads();

    int t  = blockIdx.x * blockDim.x + threadIdx.x;   // 0 .. Tq-1
    int p0 = t << 2;
    int b  = p0 >> 20;
    int n  = (p0 >> 4) & (Nn - 1);
    int o  = t & 3;                                    // own k-quad (= lane&3)

    int4 jj = ((const int4*)idx)[t];                   // own quad's neighbor indices

    // issue coord gathers early; consumed after the feature phase
    const float4* cb = g_coordsPad + (size_t)b * Nn;
    float4 ce = __ldg(cb + n);
    float4 c0 = __ldg(cb + jj.x);
    float4 c1 = __ldg(cb + jj.y);
    float4 c2 = __ldg(cb + jj.z);
    float4 c3 = __ldg(cb + jj.w);

    const float4* fT = (const float4*)(g_featT + (size_t)b * Nn * 16);
    float4* smg = sm + (threadIdx.x >> 2) * 68;

    // ---- cooperative gather: iteration u stages quad u's 4 rows ----------
#pragma unroll
    for (int u = 0; u < 4; u++) {
        int j0 = __shfl_sync(0xffffffffu, jj.x, u, 4);
        int j1 = __shfl_sync(0xffffffffu, jj.y, u, 4);
        int j2 = __shfl_sync(0xffffffffu, jj.z, u, 4);
        int j3 = __shfl_sync(0xffffffffu, jj.w, u, 4);
        float4 v0 = __ldg(fT + (size_t)j0 * 4 + o);    // chunk o of row j0
        float4 v1 = __ldg(fT + (size_t)j1 * 4 + o);
        float4 v2 = __ldg(fT + (size_t)j2 * 4 + o);
        float4 v3 = __ldg(fT + (size_t)j3 * 4 + o);
        int sw = o ^ u;                                // XOR swizzle position
        smg[(4 * u + 0) * 4 + sw] = v0;
        smg[(4 * u + 1) * 4 + sw] = v1;
        smg[(4 * u + 2) * 4 + sw] = v2;
        smg[(4 * u + 3) * 4 + sw] = v3;
    }
    __syncwarp();

    // ---- read back own quad, store fully-coalesced channel planes --------
    float* ob = out + (size_t)b * 32 * NK + (size_t)n * 16 + 4 * o;
#pragma unroll
    for (int q = 0; q < 4; q++) {
        int sw = q ^ o;
        float4 A = smg[(4 * o + 0) * 4 + sw];          // chunk q of own neighbor 0..3
        float4 B = smg[(4 * o + 1) * 4 + sw];
        float4 C = smg[(4 * o + 2) * 4 + sw];
        float4 E = smg[(4 * o + 3) * 4 + sw];
        __stcs((float4*)(ob + (size_t)(4 * q + 0) * NK), make_float4(A.x, B.x, C.x, E.x));
        __stcs((float4*)(ob + (size_t)(4 * q + 1) * NK), make_float4(A.y, B.y, C.y, E.y));
        __stcs((float4*)(ob + (size_t)(4 * q + 2) * NK), make_float4(A.z, B.z, C.z, E.z));
        __stcs((float4*)(ob + (size_t)(4 * q + 3) * NK), make_float4(A.w, B.w, C.w, E.w));
    }

    // ---- conv half: recomputed geometry ------------------------------------
    float rx, ry, rz;
    rx = ce.x - c0.x; ry = ce.y - c0.y; rz = ce.z - c0.z;
    float d0 = sqrtf(rx * rx + ry * ry + rz * rz);
    rx = ce.x - c1.x; ry = ce.y - c1.y; rz = ce.z - c1.z;
    float d1 = sqrtf(rx * rx + ry * ry + rz * rz);
    rx = ce.x - c2.x; ry = ce.y - c2.y; rz = ce.z - c2.z;
    float d2 = sqrtf(rx * rx + ry * ry + rz * rz);
    rx = ce.x - c3.x; ry = ce.y - c3.y; rz = ce.z - c3.z;
    float d3 = sqrtf(rx * rx + ry * ry + rz * rz);

    float* o2 = ob + (size_t)16 * NK;
#pragma unroll
    for (int d = 0; d < 16; d++) {
        float4 w1 = sc1[d], w2 = sc2[d];
        float ecom = fmaf(w1.y, ce.x, fmaf(w1.z, ce.y, fmaf(w1.w, ce.z, w2.w)));
        float v0 = fmaf(w1.x, d0, fmaf(w2.x, c0.x, fmaf(w2.y, c0.y, fmaf(w2.z, c0.z, ecom))));
        float v1 = fmaf(w1.x, d1, fmaf(w2.x, c1.x, fmaf(w2.y, c1.y, fmaf(w2.z, c1.z, ecom))));
        float v2 = fmaf(w1.x, d2, fmaf(w2.x, c2.x, fmaf(w2.y, c2.y, fmaf(w2.z, c2.z, ecom))));
        float v3 = fmaf(w1.x, d3, fmaf(w2.x, c3.x, fmaf(w2.y, c3.y, fmaf(w2.z, c3.z, ecom))));
        __stcs((float4*)(o2 + (size_t)d * NK),
               make_float4(fmaxf(v0, 0.f), fmaxf(v1, 0.f), fmaxf(v2, 0.f), fmaxf(v3, 0.f)));
    }
}

// ---------------------------------------------------------------------------
extern "C" void kernel_launch(void* const* d_in, const int* in_sizes, int n_in,
                              void* d_out, int out_size) {
    const float* coords = (const float*)d_in[0];
    const float* feats  = (const float*)d_in[1];
    const int*   idx    = (const int*)d_in[2];
    const float* W      = (const float*)d_in[3];
    const float* bias   = (const float*)d_in[4];
    const float* gamma  = (const float*)d_in[5];
    const float* beta   = (const float*)d_in[6];
    float*       out    = (float*)d_out;

    k_pad<<<(Bsz * Nn / 4) / 256, 256>>>(coords);
    k_stats<<<T8 / 256, 256>>>(idx, feats);
    k_finalize<<<1, 64>>>(W, bias, gamma, beta);
    k_main<<<Tq / 128, 128>>>(idx, out);
}